// round 8
// baseline (speedup 1.0000x reference)
#include <cuda_runtime.h>
#include <cstdint>

#define NIMG 64
#define CCH  256
#define HH28 28
#define HWSZ 784
#define NHW  50176
#define NTILES 392

// smem: 2 stages, each A(128 rows x 80B) + B(128 rows x 80B)
#define AROW 80
#define A_BYTES (128 * AROW)
#define STAGE (2 * A_BYTES)

// ---------------------------------------------------------------- helpers
__device__ __forceinline__ uint32_t smem_u32(const void* p) {
    uint32_t a;
    asm("{ .reg .u64 t; cvta.to.shared.u64 t, %1; cvt.u32.u64 %0, t; }" : "=r"(a) : "l"(p));
    return a;
}
__device__ __forceinline__ void cpa16(uint32_t dst, const void* src, int sz) {
    asm volatile("cp.async.cg.shared.global [%0], [%1], 16, %2;"
                 :: "r"(dst), "l"(src), "r"(sz) : "memory");
}
__device__ __forceinline__ void mma_s8(int* d, const uint32_t* a, const uint32_t* b) {
    asm volatile(
        "mma.sync.aligned.m16n8k32.row.col.s32.s8.s8.s32 "
        "{%0,%1,%2,%3}, {%4,%5,%6,%7}, {%8,%9}, {%0,%1,%2,%3};"
        : "+r"(d[0]), "+r"(d[1]), "+r"(d[2]), "+r"(d[3])
        : "r"(a[0]), "r"(a[1]), "r"(a[2]), "r"(a[3]), "r"(b[0]), "r"(b[1]));
}

// ---------------------------------------------------------------- scratch
__device__ char  g_xb1[(size_t)NHW * CCH];       // binarized x, NHWC int8
__device__ char  g_xb2[(size_t)NHW * CCH];       // binarized BN1 out, NHWC int8
__device__ char  g_wb1[9 * CCH * CCH];           // [tap][cout][cin] int8
__device__ char  g_wb2[9 * CCH * CCH];
__device__ float g_xT[(size_t)CCH * NHW];        // residual, [c][m]
__device__ short g_y1[(size_t)CCH * NHW];        // conv1 out, col-major
__device__ float g_y2[(size_t)CCH * NHW];        // conv2+resid, col-major
__device__ float g_s1[CCH], g_bi1[CCH], g_s2[CCH], g_bi2[CCH];

// -------- K1: binarize x -> NHWC int8, residual -> [c][m] fp32
__global__ void prep_x_kernel(const float* __restrict__ x,
                              char* __restrict__ xb1,
                              float* __restrict__ xT) {
    __shared__ float t[32][33];
    int tx = threadIdx.x, ty = threadIdx.y;
    int n  = blockIdx.z;
    int c0 = blockIdx.y * 32;
    int p0 = blockIdx.x * 32;
    #pragma unroll
    for (int j = 0; j < 4; j++) {
        int c = c0 + ty + j * 8;
        int p = p0 + tx;
        float v = 0.f;
        if (p < HWSZ) {
            v = x[((size_t)n * CCH + c) * HWSZ + p];
            xT[(size_t)c * NHW + n * HWSZ + p] = v;
        }
        t[ty + j * 8][tx] = v;
    }
    __syncthreads();
    #pragma unroll
    for (int j = 0; j < 4; j++) {
        int p = p0 + ty + j * 8;
        if (p < HWSZ) {
            float v = t[tx][ty + j * 8];
            xb1[((size_t)(n * HWSZ + p)) * CCH + c0 + tx] = (v >= 0.f) ? 1 : -1;
        }
    }
}

// -------- K2: binarize weights -> [tap][cout][cin] int8
__global__ void prep_w_kernel(const float* __restrict__ w, char* __restrict__ wb) {
    int idx = blockIdx.x * 256 + threadIdx.x;     // cout*256 + cin
    const float* p = w + (size_t)idx * 9;
    #pragma unroll
    for (int t = 0; t < 9; t++)
        wb[(size_t)t * 65536 + idx] = (p[t] >= 0.f) ? 1 : -1;
}

// -------- conv: int8 mma.sync implicit GEMM, col-major out
// grid (392, 2): x = M tile (128 pixels), y = cout half (128)
template <bool RESID>
__global__ void __launch_bounds__(256)
conv_kernel(const char* __restrict__ xb,
            const char* __restrict__ wb,
            const float* __restrict__ resid,
            void* __restrict__ outp) {
    __shared__ __align__(16) char sm[2][STAGE];

    int tid = threadIdx.x, wid = tid >> 5, lane = tid & 31;
    int g = lane >> 2, tg = lane & 3;
    int warpM = wid & 3, warpN = wid >> 2;

    // A-load decode: this thread owns units tid and tid+256 (row = unit>>2, u = unit&3)
    int arow[2], au[2], nbb[2], hh0[2], ww0[2];
    #pragma unroll
    for (int i = 0; i < 2; i++) {
        int unit = tid + 256 * i;
        arow[i] = unit >> 2; au[i] = unit & 3;
        int m = blockIdx.x * 128 + arow[i];
        int n = m / HWSZ;
        int hw = m - n * HWSZ;
        int h = hw / HH28;
        nbb[i] = n * HWSZ; hh0[i] = h; ww0[i] = hw - h * HH28;
    }
    const char* wbase = wb + (size_t)(blockIdx.y * 128) * CCH;

    // async-load one chunk (tap, cc) into stage s
    auto issue = [&](int chunk, int s) {
        int tap = chunk >> 2, cc = chunk & 3;
        int dy = tap / 3 - 1, dx = tap - (tap / 3) * 3 - 1;
        uint32_t As = smem_u32(sm[s]);
        uint32_t Bs = As + A_BYTES;
        #pragma unroll
        for (int i = 0; i < 2; i++) {
            int h2 = hh0[i] + dy, w2 = ww0[i] + dx;
            bool ok = ((unsigned)h2 < 28u) & ((unsigned)w2 < 28u);
            const char* src = ok
                ? xb + ((size_t)(nbb[i] + h2 * HH28 + w2)) * CCH + cc * 64 + au[i] * 16
                : xb;
            cpa16(As + arow[i] * AROW + au[i] * 16, src, ok ? 16 : 0);
        }
        const char* wsrc = wbase + (size_t)tap * 65536 + cc * 64;
        #pragma unroll
        for (int i = 0; i < 2; i++) {
            int unit = tid + 256 * i;
            int n = unit >> 2, u = unit & 3;
            cpa16(Bs + n * AROW + u * 16, wsrc + (size_t)n * CCH + u * 16, 16);
        }
        asm volatile("cp.async.commit_group;" ::: "memory");
    };

    int acc[2][8][4];
    #pragma unroll
    for (int mi = 0; mi < 2; mi++)
        #pragma unroll
        for (int ni = 0; ni < 8; ni++)
            #pragma unroll
            for (int j = 0; j < 4; j++) acc[mi][ni][j] = 0;

    issue(0, 0);
    #pragma unroll 1
    for (int chunk = 0; chunk < 36; ++chunk) {
        int s = chunk & 1;
        if (chunk + 1 < 36) {
            issue(chunk + 1, s ^ 1);
            asm volatile("cp.async.wait_group 1;" ::: "memory");
        } else {
            asm volatile("cp.async.wait_group 0;" ::: "memory");
        }
        __syncthreads();

        const char* As = sm[s];
        const char* Bs = sm[s] + A_BYTES;
        #pragma unroll
        for (int ks = 0; ks < 2; ks++) {
            int ko = ks * 32;
            uint32_t a[2][4], b[8][2];
            #pragma unroll
            for (int mi = 0; mi < 2; mi++) {
                int r = warpM * 32 + mi * 16 + g;
                a[mi][0] = *reinterpret_cast<const uint32_t*>(As + r * AROW + ko + tg * 4);
                a[mi][1] = *reinterpret_cast<const uint32_t*>(As + (r + 8) * AROW + ko + tg * 4);
                a[mi][2] = *reinterpret_cast<const uint32_t*>(As + r * AROW + ko + 16 + tg * 4);
                a[mi][3] = *reinterpret_cast<const uint32_t*>(As + (r + 8) * AROW + ko + 16 + tg * 4);
            }
            #pragma unroll
            for (int ni = 0; ni < 8; ni++) {
                int c = warpN * 64 + ni * 8 + g;
                b[ni][0] = *reinterpret_cast<const uint32_t*>(Bs + c * AROW + ko + tg * 4);
                b[ni][1] = *reinterpret_cast<const uint32_t*>(Bs + c * AROW + ko + 16 + tg * 4);
            }
            #pragma unroll
            for (int mi = 0; mi < 2; mi++)
                #pragma unroll
                for (int ni = 0; ni < 8; ni++)
                    mma_s8(acc[mi][ni], a[mi], b[ni]);
        }
        __syncthreads();
    }

    // epilogue: col-major [c][m]
    #pragma unroll
    for (int mi = 0; mi < 2; mi++) {
        size_t m0 = (size_t)blockIdx.x * 128 + warpM * 32 + mi * 16 + g;
        #pragma unroll
        for (int ni = 0; ni < 8; ni++) {
            int c0 = blockIdx.y * 128 + warpN * 64 + ni * 8 + 2 * tg;
            #pragma unroll
            for (int j = 0; j < 4; j++) {
                size_t m = m0 + (j >> 1) * 8;
                int c = c0 + (j & 1);
                size_t o = (size_t)c * NHW + m;
                if (RESID) {
                    reinterpret_cast<float*>(outp)[o] = (float)acc[mi][ni][j] + resid[o];
                } else {
                    reinterpret_cast<short*>(outp)[o] = (short)acc[mi][ni][j];
                }
            }
        }
    }
}

// -------- stats: per-channel fused BN scale/bias
template <typename T>
__global__ void stats_kernel(const T* __restrict__ ycm,
                             const float* __restrict__ gamma, const float* __restrict__ beta,
                             float* __restrict__ scl, float* __restrict__ bia) {
    int c = blockIdx.x;
    const T* p = ycm + (size_t)c * NHW;
    float s = 0.f, q = 0.f;
    for (int i = threadIdx.x; i < NHW; i += 256) {
        float v = (float)p[i];
        s += v; q += v * v;
    }
    __shared__ float rs[256], rq[256];
    rs[threadIdx.x] = s; rq[threadIdx.x] = q;
    __syncthreads();
    for (int o = 128; o > 0; o >>= 1) {
        if (threadIdx.x < o) { rs[threadIdx.x] += rs[threadIdx.x + o]; rq[threadIdx.x] += rq[threadIdx.x + o]; }
        __syncthreads();
    }
    if (threadIdx.x == 0) {
        float mean = rs[0] / (float)NHW;
        float var  = rq[0] / (float)NHW - mean * mean;
        float inv  = rsqrtf(var + 1e-5f);
        float sc   = gamma[c] * inv;
        scl[c] = sc;
        bia[c] = beta[c] - mean * sc;
    }
}

// -------- binarize BN1 output: [c][m] int16 -> [m][c] int8 +-1
__global__ void binarize_kernel(const short* __restrict__ ycm,
                                const float* __restrict__ scl, const float* __restrict__ bia,
                                char* __restrict__ xb2) {
    __shared__ short t[32][33];
    __shared__ float sc[32], bi[32];
    int tx = threadIdx.x, ty = threadIdx.y;
    int c0 = blockIdx.y * 32, m0 = blockIdx.x * 32;
    if (ty == 0) { sc[tx] = scl[c0 + tx]; bi[tx] = bia[c0 + tx]; }
    #pragma unroll
    for (int j = 0; j < 4; j++) {
        int c = c0 + ty + j * 8;
        t[ty + j * 8][tx] = ycm[(size_t)c * NHW + m0 + tx];
    }
    __syncthreads();
    #pragma unroll
    for (int j = 0; j < 4; j++) {
        int m = m0 + ty + j * 8;
        float v = (float)t[tx][ty + j * 8] * sc[tx] + bi[tx];
        xb2[(size_t)m * CCH + c0 + tx] = (v >= 0.f) ? 1 : -1;
    }
}

// -------- final: BN2 + hardtanh + NCHW
__global__ void final_kernel(const float* __restrict__ y2,
                             const float* __restrict__ scl, const float* __restrict__ bia,
                             float* __restrict__ out) {
    size_t total = (size_t)CCH * NHW;
    for (size_t idx = (size_t)blockIdx.x * blockDim.x + threadIdx.x; idx < total;
         idx += (size_t)gridDim.x * blockDim.x) {
        unsigned c = (unsigned)(idx / NHW);
        unsigned r = (unsigned)(idx - (size_t)c * NHW);
        unsigned n = r / HWSZ;
        unsigned hw = r - n * HWSZ;
        float v = y2[idx] * scl[c] + bia[c];
        v = fminf(fmaxf(v, -1.f), 1.f);
        out[((size_t)n * CCH + c) * HWSZ + hw] = v;
    }
}

// ---------------------------------------------------------------- launcher
extern "C" void kernel_launch(void* const* d_in, const int* in_sizes, int n_in,
                              void* d_out, int out_size) {
    const float* x   = (const float*)d_in[0];
    const float* w1  = (const float*)d_in[1];
    const float* w2  = (const float*)d_in[2];
    const float* ga1 = (const float*)d_in[3];
    const float* be1 = (const float*)d_in[4];
    const float* ga2 = (const float*)d_in[5];
    const float* be2 = (const float*)d_in[6];
    float* out = (float*)d_out;

    char *xb1, *xb2, *wb1, *wb2;
    float *xT, *y2, *s1, *bi1, *s2, *bi2;
    short* y1;
    cudaGetSymbolAddress((void**)&xb1, g_xb1);
    cudaGetSymbolAddress((void**)&xb2, g_xb2);
    cudaGetSymbolAddress((void**)&wb1, g_wb1);
    cudaGetSymbolAddress((void**)&wb2, g_wb2);
    cudaGetSymbolAddress((void**)&xT,  g_xT);
    cudaGetSymbolAddress((void**)&y1,  g_y1);
    cudaGetSymbolAddress((void**)&y2,  g_y2);
    cudaGetSymbolAddress((void**)&s1,  g_s1);
    cudaGetSymbolAddress((void**)&bi1, g_bi1);
    cudaGetSymbolAddress((void**)&s2,  g_s2);
    cudaGetSymbolAddress((void**)&bi2, g_bi2);

    prep_x_kernel<<<dim3(25, 8, 64), dim3(32, 8)>>>(x, xb1, xT);
    prep_w_kernel<<<256, 256>>>(w1, wb1);
    prep_w_kernel<<<256, 256>>>(w2, wb2);

    conv_kernel<false><<<dim3(NTILES, 2), 256>>>(xb1, wb1, nullptr, (void*)y1);
    stats_kernel<short><<<256, 256>>>(y1, ga1, be1, s1, bi1);
    binarize_kernel<<<dim3(1568, 8), dim3(32, 8)>>>(y1, s1, bi1, xb2);

    conv_kernel<true><<<dim3(NTILES, 2), 256>>>(xb2, wb2, xT, (void*)y2);
    stats_kernel<float><<<256, 256>>>(y2, ga2, be2, s2, bi2);
    final_kernel<<<1184, 256>>>(y2, s2, bi2, out);
}

// round 9
// speedup vs baseline: 1.6768x; 1.6768x over previous
#include <cuda_runtime.h>
#include <cstdint>

#define NIMG 64
#define CCH  256
#define HH28 28
#define HWSZ 784
#define NHW  50176
#define NT2  196          // winograd tiles per image (14x14)
#define MWIN 12544        // 64*196 tile-rows
#define UPLANE (MWIN * CCH)   // bytes per U[t] plane (int8)
#define VPLANE (CCH * CCH)

// smem for wino gemm: 2 stages, each A(64 x 80B) + B(64 x 80B)
#define AROW 80
#define HALF_BYTES (64 * AROW)
#define STAGE (2 * HALF_BYTES)

// ---------------------------------------------------------------- helpers
__device__ __forceinline__ uint32_t smem_u32(const void* p) {
    uint32_t a;
    asm("{ .reg .u64 t; cvta.to.shared.u64 t, %1; cvt.u32.u64 %0, t; }" : "=r"(a) : "l"(p));
    return a;
}
__device__ __forceinline__ void cpa16(uint32_t dst, const void* src) {
    asm volatile("cp.async.cg.shared.global [%0], [%1], 16;"
                 :: "r"(dst), "l"(src) : "memory");
}
__device__ __forceinline__ void mma_s8(int* d, const uint32_t* a, const uint32_t* b) {
    asm volatile(
        "mma.sync.aligned.m16n8k32.row.col.s32.s8.s8.s32 "
        "{%0,%1,%2,%3}, {%4,%5,%6,%7}, {%8,%9}, {%0,%1,%2,%3};"
        : "+r"(d[0]), "+r"(d[1]), "+r"(d[2]), "+r"(d[3])
        : "r"(a[0]), "r"(a[1]), "r"(a[2]), "r"(a[3]), "r"(b[0]), "r"(b[1]));
}

// ---------------------------------------------------------------- scratch
__device__ __align__(256) char  g_xb1[(size_t)NHW * CCH];   // binarized x, NHWC int8
__device__ __align__(256) char  g_xb2[(size_t)NHW * CCH];   // binarized BN1 out, NHWC int8
__device__ __align__(256) char  g_U[(size_t)16 * UPLANE];   // winograd input transform
__device__ __align__(256) char  g_V1[16 * VPLANE];          // winograd weight transform
__device__ __align__(256) char  g_V2[16 * VPLANE];
__device__ float g_xT[(size_t)CCH * NHW];                   // residual, [c][m]
__device__ short g_y1[(size_t)CCH * NHW];                   // conv1 out, col-major
__device__ float g_y2[(size_t)CCH * NHW];                   // conv2+resid, col-major
__device__ float g_s1[CCH], g_bi1[CCH], g_s2[CCH], g_bi2[CCH];

// -------- K1: binarize x -> NHWC int8, residual -> [c][m] fp32
__global__ void prep_x_kernel(const float* __restrict__ x,
                              char* __restrict__ xb1,
                              float* __restrict__ xT) {
    __shared__ float t[32][33];
    int tx = threadIdx.x, ty = threadIdx.y;
    int n  = blockIdx.z;
    int c0 = blockIdx.y * 32;
    int p0 = blockIdx.x * 32;
    #pragma unroll
    for (int j = 0; j < 4; j++) {
        int c = c0 + ty + j * 8;
        int p = p0 + tx;
        float v = 0.f;
        if (p < HWSZ) {
            v = x[((size_t)n * CCH + c) * HWSZ + p];
            xT[(size_t)c * NHW + n * HWSZ + p] = v;
        }
        t[ty + j * 8][tx] = v;
    }
    __syncthreads();
    #pragma unroll
    for (int j = 0; j < 4; j++) {
        int p = p0 + ty + j * 8;
        if (p < HWSZ) {
            float v = t[tx][ty + j * 8];
            xb1[((size_t)(n * HWSZ + p)) * CCH + c0 + tx] = (v >= 0.f) ? 1 : -1;
        }
    }
}

// -------- wino V: w (OIHW f32) -> V[t][cout*256+cin] int8, V = (2G) sign(w) (2G)^T
__global__ void wino_v_kernel(const float* __restrict__ w, char* __restrict__ V) {
    int idx = blockIdx.x * 256 + threadIdx.x;   // cout*256 + cin
    const float* p = w + (size_t)idx * 9;
    int b[3][3];
    #pragma unroll
    for (int i = 0; i < 3; i++)
        #pragma unroll
        for (int j = 0; j < 3; j++)
            b[i][j] = (p[i * 3 + j] >= 0.f) ? 1 : -1;
    int g[4][3];
    #pragma unroll
    for (int j = 0; j < 3; j++) {
        g[0][j] = 2 * b[0][j];
        g[1][j] = b[0][j] + b[1][j] + b[2][j];
        g[2][j] = b[0][j] - b[1][j] + b[2][j];
        g[3][j] = 2 * b[2][j];
    }
    #pragma unroll
    for (int i = 0; i < 4; i++) {
        int v0 = 2 * g[i][0];
        int v1 = g[i][0] + g[i][1] + g[i][2];
        int v2 = g[i][0] - g[i][1] + g[i][2];
        int v3 = 2 * g[i][2];
        V[(size_t)(i * 4 + 0) * VPLANE + idx] = (char)v0;
        V[(size_t)(i * 4 + 1) * VPLANE + idx] = (char)v1;
        V[(size_t)(i * 4 + 2) * VPLANE + idx] = (char)v2;
        V[(size_t)(i * 4 + 3) * VPLANE + idx] = (char)v3;
    }
}

// -------- wino U: xb NHWC int8 -> U[t][tile*256+c] int8  (B^T d B, |U|<=4)
__global__ void wino_u_kernel(const char* __restrict__ xb, char* __restrict__ U) {
    int item = blockIdx.x * 256 + threadIdx.x;   // tile*64 + cgroup
    int tile = item >> 6;
    int cg = item & 63;                          // 4 channels per thread
    int n = tile / NT2;
    int rt = tile - n * NT2;
    int ty = rt / 14, tx = rt - ty * 14;
    int h0 = 2 * ty - 1, w0 = 2 * tx - 1;
    const char* base = xb + ((size_t)n * HWSZ) * CCH + cg * 4;

    uint32_t d[4][4];
    #pragma unroll
    for (int i = 0; i < 4; i++) {
        int h = h0 + i;
        #pragma unroll
        for (int j = 0; j < 4; j++) {
            int w = w0 + j;
            d[i][j] = (((unsigned)h < 28u) & ((unsigned)w < 28u))
                ? *reinterpret_cast<const uint32_t*>(base + (size_t)(h * HH28 + w) * CCH)
                : 0u;
        }
    }
    uint32_t r[4][4];
    #pragma unroll
    for (int j = 0; j < 4; j++) {
        r[0][j] = __vsub4(d[0][j], d[2][j]);
        r[1][j] = __vadd4(d[1][j], d[2][j]);
        r[2][j] = __vsub4(d[2][j], d[1][j]);
        r[3][j] = __vsub4(d[1][j], d[3][j]);
    }
    #pragma unroll
    for (int i = 0; i < 4; i++) {
        uint32_t u0 = __vsub4(r[i][0], r[i][2]);
        uint32_t u1 = __vadd4(r[i][1], r[i][2]);
        uint32_t u2 = __vsub4(r[i][2], r[i][1]);
        uint32_t u3 = __vsub4(r[i][1], r[i][3]);
        size_t off = (size_t)tile * CCH + cg * 4;
        *reinterpret_cast<uint32_t*>(U + (size_t)(i * 4 + 0) * UPLANE + off) = u0;
        *reinterpret_cast<uint32_t*>(U + (size_t)(i * 4 + 1) * UPLANE + off) = u1;
        *reinterpret_cast<uint32_t*>(U + (size_t)(i * 4 + 2) * UPLANE + off) = u2;
        *reinterpret_cast<uint32_t*>(U + (size_t)(i * 4 + 3) * UPLANE + off) = u3;
    }
}

// -------- wino GEMM: for t in 0..15: Mhat = U[t]*V[t]^T, fold into Y, write col-major
// grid (196, 4): x = M tile (64 wino rows), y = cout tile (64)
template <bool RESID>
__global__ void __launch_bounds__(256, 2)
wino_gemm(const char* __restrict__ U,
          const char* __restrict__ V,
          const float* __restrict__ resid,
          void* __restrict__ outp) {
    __shared__ __align__(16) char sm[2][STAGE];

    int tid = threadIdx.x, wid = tid >> 5, lane = tid & 31;
    int g = lane >> 2, tg = lane & 3;
    int warpM = wid & 3, warpN = wid >> 2;    // 4 x 2 warps, warp tile 16x32

    int lrow = tid >> 2, lu = tid & 3;        // one 16B unit per thread per matrix
    const char* Ubase = U + ((size_t)blockIdx.x * 64 + lrow) * CCH + lu * 16;
    const char* Vbase = V + ((size_t)blockIdx.y * 64 + lrow) * CCH + lu * 16;
    uint32_t dstA = smem_u32(&sm[0][0]) + lrow * AROW + lu * 16;
    uint32_t dstB = dstA + HALF_BYTES;

    auto issue = [&](int chunk, int s) {
        int t = chunk >> 2, kc = chunk & 3;
        size_t koff = (size_t)t * UPLANE + kc * 64;
        cpa16(dstA + s * STAGE, Ubase + koff);
        cpa16(dstB + s * STAGE, Vbase + (size_t)t * VPLANE + kc * 64);
        asm volatile("cp.async.commit_group;" ::: "memory");
    };

    int Y[4][4][4];
    int acc[4][4];
    #pragma unroll
    for (int ni = 0; ni < 4; ni++)
        #pragma unroll
        for (int j = 0; j < 4; j++) {
            acc[ni][j] = 0;
            #pragma unroll
            for (int p = 0; p < 4; p++) Y[ni][j][p] = 0;
        }

    issue(0, 0);
    #pragma unroll 1
    for (int chunk = 0; chunk < 64; ++chunk) {
        int s = chunk & 1;
        if (chunk + 1 < 64) {
            issue(chunk + 1, s ^ 1);
            asm volatile("cp.async.wait_group 1;" ::: "memory");
        } else {
            asm volatile("cp.async.wait_group 0;" ::: "memory");
        }
        __syncthreads();

        const char* As = sm[s];
        const char* Bs = sm[s] + HALF_BYTES;
        #pragma unroll
        for (int ks = 0; ks < 2; ks++) {
            int ko = ks * 32;
            uint32_t a[4], b[4][2];
            {
                int r = warpM * 16 + g;
                a[0] = *reinterpret_cast<const uint32_t*>(As + r * AROW + ko + tg * 4);
                a[1] = *reinterpret_cast<const uint32_t*>(As + (r + 8) * AROW + ko + tg * 4);
                a[2] = *reinterpret_cast<const uint32_t*>(As + r * AROW + ko + 16 + tg * 4);
                a[3] = *reinterpret_cast<const uint32_t*>(As + (r + 8) * AROW + ko + 16 + tg * 4);
            }
            #pragma unroll
            for (int ni = 0; ni < 4; ni++) {
                int c = warpN * 32 + ni * 8 + g;
                b[ni][0] = *reinterpret_cast<const uint32_t*>(Bs + c * AROW + ko + tg * 4);
                b[ni][1] = *reinterpret_cast<const uint32_t*>(Bs + c * AROW + ko + 16 + tg * 4);
            }
            #pragma unroll
            for (int ni = 0; ni < 4; ni++)
                mma_s8(acc[ni], a, b[ni]);
        }
        __syncthreads();

        if ((chunk & 3) == 3) {
            // fold Mhat (acc) of t = chunk>>2 into Y, reset acc
            int t = chunk >> 2;
            int tr = t >> 2, tc = t & 3;
            int cr0 = (tr <= 2) ? 1 : 0;
            int cr1 = (tr == 0) ? 0 : ((tr == 1) ? 1 : -1);
            int cc0 = (tc <= 2) ? 1 : 0;
            int cc1 = (tc == 0) ? 0 : ((tc == 1) ? 1 : -1);
            #pragma unroll
            for (int ni = 0; ni < 4; ni++)
                #pragma unroll
                for (int j = 0; j < 4; j++) {
                    int v = acc[ni][j];
                    Y[ni][j][0] += cr0 * cc0 * v;
                    Y[ni][j][1] += cr0 * cc1 * v;
                    Y[ni][j][2] += cr1 * cc0 * v;
                    Y[ni][j][3] += cr1 * cc1 * v;
                    acc[ni][j] = 0;
                }
        }
    }

    // epilogue: each Mhat element -> 2x2 output pixels, col-major [c][m]
    #pragma unroll
    for (int j = 0; j < 4; j++) {
        int mp = blockIdx.x * 64 + warpM * 16 + g + 8 * (j >> 1);  // wino row
        int n = mp / NT2;
        int rt = mp - n * NT2;
        int ty = rt / 14, tx = rt - ty * 14;
        int mbase = n * HWSZ + (2 * ty) * HH28 + 2 * tx;
        #pragma unroll
        for (int ni = 0; ni < 4; ni++) {
            int c = blockIdx.y * 64 + warpN * 32 + ni * 8 + 2 * tg + (j & 1);
            size_t obase = (size_t)c * NHW + mbase;
            #pragma unroll
            for (int p = 0; p < 4; p++) {
                size_t o = obase + (p >> 1) * HH28 + (p & 1);
                int val = Y[ni][j][p] >> 2;   // exact /4
                if (RESID) {
                    reinterpret_cast<float*>(outp)[o] = (float)val + resid[o];
                } else {
                    reinterpret_cast<short*>(outp)[o] = (short)val;
                }
            }
        }
    }
}

// -------- stats: per-channel fused BN scale/bias
template <typename T>
__global__ void stats_kernel(const T* __restrict__ ycm,
                             const float* __restrict__ gamma, const float* __restrict__ beta,
                             float* __restrict__ scl, float* __restrict__ bia) {
    int c = blockIdx.x;
    const T* p = ycm + (size_t)c * NHW;
    float s = 0.f, q = 0.f;
    for (int i = threadIdx.x; i < NHW; i += 256) {
        float v = (float)p[i];
        s += v; q += v * v;
    }
    __shared__ float rs[256], rq[256];
    rs[threadIdx.x] = s; rq[threadIdx.x] = q;
    __syncthreads();
    for (int o = 128; o > 0; o >>= 1) {
        if (threadIdx.x < o) { rs[threadIdx.x] += rs[threadIdx.x + o]; rq[threadIdx.x] += rq[threadIdx.x + o]; }
        __syncthreads();
    }
    if (threadIdx.x == 0) {
        float mean = rs[0] / (float)NHW;
        float var  = rq[0] / (float)NHW - mean * mean;
        float inv  = rsqrtf(var + 1e-5f);
        float sc   = gamma[c] * inv;
        scl[c] = sc;
        bia[c] = beta[c] - mean * sc;
    }
}

// -------- binarize BN1 output: [c][m] int16 -> [m][c] int8 +-1
__global__ void binarize_kernel(const short* __restrict__ ycm,
                                const float* __restrict__ scl, const float* __restrict__ bia,
                                char* __restrict__ xb2) {
    __shared__ short t[32][33];
    __shared__ float sc[32], bi[32];
    int tx = threadIdx.x, ty = threadIdx.y;
    int c0 = blockIdx.y * 32, m0 = blockIdx.x * 32;
    if (ty == 0) { sc[tx] = scl[c0 + tx]; bi[tx] = bia[c0 + tx]; }
    #pragma unroll
    for (int j = 0; j < 4; j++) {
        int c = c0 + ty + j * 8;
        t[ty + j * 8][tx] = ycm[(size_t)c * NHW + m0 + tx];
    }
    __syncthreads();
    #pragma unroll
    for (int j = 0; j < 4; j++) {
        int m = m0 + ty + j * 8;
        float v = (float)t[tx][ty + j * 8] * sc[tx] + bi[tx];
        xb2[(size_t)m * CCH + c0 + tx] = (v >= 0.f) ? 1 : -1;
    }
}

// -------- final: BN2 + hardtanh + NCHW
__global__ void final_kernel(const float* __restrict__ y2,
                             const float* __restrict__ scl, const float* __restrict__ bia,
                             float* __restrict__ out) {
    size_t total = (size_t)CCH * NHW;
    for (size_t idx = (size_t)blockIdx.x * blockDim.x + threadIdx.x; idx < total;
         idx += (size_t)gridDim.x * blockDim.x) {
        unsigned c = (unsigned)(idx / NHW);
        unsigned r = (unsigned)(idx - (size_t)c * NHW);
        unsigned n = r / HWSZ;
        unsigned hw = r - n * HWSZ;
        float v = y2[idx] * scl[c] + bia[c];
        v = fminf(fmaxf(v, -1.f), 1.f);
        out[((size_t)n * CCH + c) * HWSZ + hw] = v;
    }
}

// ---------------------------------------------------------------- launcher
extern "C" void kernel_launch(void* const* d_in, const int* in_sizes, int n_in,
                              void* d_out, int out_size) {
    const float* x   = (const float*)d_in[0];
    const float* w1  = (const float*)d_in[1];
    const float* w2  = (const float*)d_in[2];
    const float* ga1 = (const float*)d_in[3];
    const float* be1 = (const float*)d_in[4];
    const float* ga2 = (const float*)d_in[5];
    const float* be2 = (const float*)d_in[6];
    float* out = (float*)d_out;

    char *xb1, *xb2, *U, *V1, *V2;
    float *xT, *y2, *s1, *bi1, *s2, *bi2;
    short* y1;
    cudaGetSymbolAddress((void**)&xb1, g_xb1);
    cudaGetSymbolAddress((void**)&xb2, g_xb2);
    cudaGetSymbolAddress((void**)&U,   g_U);
    cudaGetSymbolAddress((void**)&V1,  g_V1);
    cudaGetSymbolAddress((void**)&V2,  g_V2);
    cudaGetSymbolAddress((void**)&xT,  g_xT);
    cudaGetSymbolAddress((void**)&y1,  g_y1);
    cudaGetSymbolAddress((void**)&y2,  g_y2);
    cudaGetSymbolAddress((void**)&s1,  g_s1);
    cudaGetSymbolAddress((void**)&bi1, g_bi1);
    cudaGetSymbolAddress((void**)&s2,  g_s2);
    cudaGetSymbolAddress((void**)&bi2, g_bi2);

    prep_x_kernel<<<dim3(25, 8, 64), dim3(32, 8)>>>(x, xb1, xT);
    wino_v_kernel<<<256, 256>>>(w1, V1);
    wino_v_kernel<<<256, 256>>>(w2, V2);

    wino_u_kernel<<<MWIN * 64 / 256, 256>>>(xb1, U);
    wino_gemm<false><<<dim3(196, 4), 256>>>(U, V1, nullptr, (void*)y1);
    stats_kernel<short><<<256, 256>>>(y1, ga1, be1, s1, bi1);
    binarize_kernel<<<dim3(1568, 8), dim3(32, 8)>>>(y1, s1, bi1, xb2);

    wino_u_kernel<<<MWIN * 64 / 256, 256>>>(xb2, U);
    wino_gemm<true><<<dim3(196, 4), 256>>>(U, V2, xT, (void*)y2);
    stats_kernel<float><<<256, 256>>>(y2, ga2, be2, s2, bi2);
    final_kernel<<<1184, 256>>>(y2, s2, bi2, out);
}